// round 15
// baseline (speedup 1.0000x reference)
#include <cuda_runtime.h>

#define NBATCH 16
#define NPT    4096
#define NQ     1024
#define NSAMP  32
#define OUT1SZ (NBATCH*3*NQ)
#define OUT2SZ (NBATCH*128*NQ)
#define MAXE   (NBATCH*NQ*NSAMP + 64)
#define FULLM  0xffffffffu

__device__ int      g_fps[NBATCH*NQ];
__device__ unsigned g_ent[MAXE];
__device__ int      g_ecnt;
__device__ float    g_ptsT[NBATCH*NPT*64];   // [b][p][c] transposed points
__device__ float    g_sx[NBATCH*NPT], g_sy[NBATCH*NPT], g_sz[NBATCH*NPT];
__device__ int      g_oi[NBATCH*NPT];        // sorted -> original index
__device__ float    g_W0[67*64], g_B0[64];
__device__ float    g_W1[64*64], g_B1[64];
__device__ float    g_W2[64*128], g_B2[128];

// ---- f32x2 packed helpers: two independent .rn fp32 ops per instruction --
__device__ __forceinline__ unsigned long long pk2(float a, float b){
    unsigned long long r; asm("mov.b64 %0,{%1,%2};":"=l"(r):"f"(a),"f"(b)); return r;
}
__device__ __forceinline__ void upk2(unsigned long long v, float&a, float&b){
    asm("mov.b64 {%0,%1},%2;":"=f"(a),"=f"(b):"l"(v));
}
__device__ __forceinline__ unsigned long long add2(unsigned long long a, unsigned long long b){
    unsigned long long r; asm("add.rn.f32x2 %0,%1,%2;":"=l"(r):"l"(a),"l"(b)); return r;
}
__device__ __forceinline__ unsigned long long mul2(unsigned long long a, unsigned long long b){
    unsigned long long r; asm("mul.rn.f32x2 %0,%1,%2;":"=l"(r):"l"(a),"l"(b)); return r;
}
__device__ __forceinline__ unsigned long long pku(unsigned lo, unsigned hi){
    unsigned long long r; asm("mov.b64 %0,{%1,%2};":"=l"(r):"r"(lo),"r"(hi)); return r;
}
__device__ __forceinline__ unsigned long long umax64(unsigned long long a, unsigned long long b){
    return a > b ? a : b;
}

// ---------------- prep: zero out2 + fold BN + transpose pts + octant sort -
__global__ void __launch_bounds__(256) prep_kernel(float* __restrict__ out2,
    const float* __restrict__ pts, const float* __restrict__ xyz,
    const float* w0,const float* b0,const float* g0,const float* be0,const float* m0,const float* v0,
    const float* w1,const float* b1,const float* g1,const float* be1,const float* m1,const float* v1,
    const float* w2,const float* b2,const float* g2,const float* be2,const float* m2,const float* v2)
{
    __shared__ float tile[64][65];
    __shared__ int   hist8[8];
    int idx = blockIdx.x*blockDim.x + threadIdx.x;
    if (idx < OUT2SZ/4) ((float4*)out2)[idx] = make_float4(0.f,0.f,0.f,0.f);
    if (blockIdx.x == 0) {
        int t = threadIdx.x;
        if (t == 0) g_ecnt = 0;
        for (int i=t;i<67*64;i+=blockDim.x){int c=i>>6,o=i&63;float s=g0[o]*rsqrtf(v0[o]+1e-5f);g_W0[i]=w0[o*67+c]*s;}
        for (int i=t;i<64*64;i+=blockDim.x){int c=i>>6,o=i&63;float s=g1[o]*rsqrtf(v1[o]+1e-5f);g_W1[i]=w1[o*64+c]*s;}
        for (int i=t;i<64*128;i+=blockDim.x){int k=i>>7,o=i&127;float s=g2[o]*rsqrtf(v2[o]+1e-5f);g_W2[i]=w2[o*64+k]*s;}
        if (t<64){float s=g0[t]*rsqrtf(v0[t]+1e-5f);g_B0[t]=(b0[t]-m0[t])*s+be0[t];}
        if (t<64){float s=g1[t]*rsqrtf(v1[t]+1e-5f);g_B1[t]=(b1[t]-m1[t])*s+be1[t];}
        if (t<128){float s=g2[t]*rsqrtf(v2[t]+1e-5f);g_B2[t]=(b2[t]-m2[t])*s+be2[t];}
    }
    // transpose: CTAs 0..1023 each handle one [64ch x 64pt] tile
    if (blockIdx.x < 1024){
        int b = blockIdx.x >> 6, pt = blockIdx.x & 63;
        int p0 = pt*64;
        const float* src = pts + (size_t)b*64*NPT;
        for (int i=threadIdx.x; i<64*64; i+=256){
            int c = i>>6, pl = i&63;
            tile[c][pl] = src[(size_t)c*NPT + p0 + pl];
        }
        __syncthreads();
        float* dst = g_ptsT + ((size_t)b*NPT + p0)*64;
        for (int i=threadIdx.x; i<64*64; i+=256){
            int pl = i>>6, c = i&63;
            dst[(size_t)pl*64 + c] = tile[c][pl];
        }
    }
    // octant counting-sort (split at 0): CTAs 1024..1039, one per batch
    if (blockIdx.x >= 1024 && blockIdx.x < 1024+NBATCH){
        int b = blockIdx.x - 1024;
        int t = threadIdx.x;
        const float* Xx = xyz + b*3*NPT;
        const float* Xy = Xx + NPT;
        const float* Xz = Xx + 2*NPT;
        if (t < 8) hist8[t] = 0;
        __syncthreads();
        for (int i=t;i<NPT;i+=256){
            int c = ((Xx[i]>0.f)?4:0)|((Xy[i]>0.f)?2:0)|((Xz[i]>0.f)?1:0);
            atomicAdd(&hist8[c],1);
        }
        __syncthreads();
        if (t==0){
            int acc=0;
            for (int i=0;i<8;i++){ int h=hist8[i]; hist8[i]=acc; acc+=h; }
        }
        __syncthreads();
        for (int i=t;i<NPT;i+=256){
            float x=Xx[i], y=Xy[i], z=Xz[i];
            int c = ((x>0.f)?4:0)|((y>0.f)?2:0)|((z>0.f)?1:0);
            int pos = atomicAdd(&hist8[c],1);
            g_sx[b*NPT+pos]=x; g_sy[b*NPT+pos]=y; g_sz[b*NPT+pos]=z;
            g_oi[b*NPT+pos]=i;
        }
    }
}

// ---------------- FPS: octant-sorted, WARP-uniform exact pruning ----------
// Each warp owns ~one octant (512 sorted pts). Skip the whole warp's update
// when lb(warp bbox)*(1-2e-6) >= wmaxdd — provably a no-op (fp32 dist error
// <= 3ulp). dd bits stay exactly equal to the reference for every point.
// Keys (ddbits<<32)|(4095-origidx): u64 order == max val then min orig idx.
__global__ void __launch_bounds__(256,1) fps_kernel(const float* __restrict__ xyz,
                                                    float* __restrict__ out1)
{
    __shared__ __align__(16) unsigned long long s_key[2][8];
    int b = blockIdx.x, t = threadIdx.x;
    int lane = t & 31, wid = t >> 5;
    const float* X = xyz + b*3*NPT;
    int sb = b*NPT + t*16;
    float px[16],py[16],pz[16],dd[16];
    unsigned lo[16];
    #pragma unroll
    for (int q=0;q<4;q++){
        float4 a  = *(const float4*)(g_sx+sb+q*4);
        float4 bv = *(const float4*)(g_sy+sb+q*4);
        float4 c  = *(const float4*)(g_sz+sb+q*4);
        int4   o4 = *(const int4*)(g_oi+sb+q*4);
        px[q*4]=a.x; px[q*4+1]=a.y; px[q*4+2]=a.z; px[q*4+3]=a.w;
        py[q*4]=bv.x;py[q*4+1]=bv.y;py[q*4+2]=bv.z;py[q*4+3]=bv.w;
        pz[q*4]=c.x; pz[q*4+1]=c.y; pz[q*4+2]=c.z; pz[q*4+3]=c.w;
        lo[q*4]=4095-o4.x; lo[q*4+1]=4095-o4.y; lo[q*4+2]=4095-o4.z; lo[q*4+3]=4095-o4.w;
    }
    // warp-level bbox: per-thread 16-pt bbox, then shfl reduce (uniform)
    float bxm=px[0],bxM=px[0],bym=py[0],byM=py[0],bzm=pz[0],bzM=pz[0];
    #pragma unroll
    for (int j=1;j<16;j++){
        bxm=fminf(bxm,px[j]); bxM=fmaxf(bxM,px[j]);
        bym=fminf(bym,py[j]); byM=fmaxf(byM,py[j]);
        bzm=fminf(bzm,pz[j]); bzM=fmaxf(bzM,pz[j]);
    }
    #pragma unroll
    for (int o=16;o;o>>=1){
        bxm=fminf(bxm,__shfl_xor_sync(FULLM,bxm,o));
        bxM=fmaxf(bxM,__shfl_xor_sync(FULLM,bxM,o));
        bym=fminf(bym,__shfl_xor_sync(FULLM,bym,o));
        byM=fmaxf(byM,__shfl_xor_sync(FULLM,byM,o));
        bzm=fminf(bzm,__shfl_xor_sync(FULLM,bzm,o));
        bzM=fmaxf(bzM,__shfl_xor_sync(FULLM,bzM,o));
    }
    unsigned long long px2[8],py2[8],pz2[8];
    #pragma unroll
    for (int p=0;p<8;p++){ px2[p]=pk2(px[2*p],px[2*p+1]); py2[p]=pk2(py[2*p],py[2*p+1]); pz2[p]=pk2(pz[2*p],pz[2*p+1]); }
    #pragma unroll
    for (int j=0;j<16;j++) dd[j]=1e10f;
    float wmaxdd = 3.4e38f;
    unsigned long long wkey = 0;
    int f = 0;
    float cx=__ldg(X), cy=__ldg(X+NPT), cz=__ldg(X+2*NPT);
    for (int it=0; it<NQ; ++it) {
        if (t == 0) g_fps[b*NQ+it] = f;
        // warp-uniform lower bound on squared distance to any point of warp
        float dxl = fmaxf(fmaxf(bxm-cx, cx-bxM), 0.f);
        float dyl = fmaxf(fmaxf(bym-cy, cy-byM), 0.f);
        float dzl = fmaxf(fmaxf(bzm-cz, cz-bzM), 0.f);
        float lb = dxl*dxl + dyl*dyl + dzl*dzl;
        if (__fmul_rn(lb, 0.999998f) < wmaxdd){   // warp-uniform branch
            unsigned long long ncx=pk2(-cx,-cx), ncy=pk2(-cy,-cy), ncz=pk2(-cz,-cz);
            #pragma unroll
            for (int p=0;p<8;p++){
                // (px-cx)^2+(py-cy)^2+(pz-cz)^2, each op .rn, left-assoc (matches XLA)
                unsigned long long dx=add2(px2[p],ncx), dy=add2(py2[p],ncy), dz=add2(pz2[p],ncz);
                unsigned long long d2=add2(add2(mul2(dx,dx),mul2(dy,dy)),mul2(dz,dz));
                float dl,dh; upk2(d2,dl,dh);
                dd[2*p]   = fminf(dd[2*p],   dl);
                dd[2*p+1] = fminf(dd[2*p+1], dh);
            }
            unsigned long long kk8[8];
            #pragma unroll
            for (int j=0;j<8;j++){
                unsigned long long ka = pku(lo[2*j],   __float_as_uint(dd[2*j]));
                unsigned long long kb = pku(lo[2*j+1], __float_as_uint(dd[2*j+1]));
                kk8[j] = umax64(ka,kb);
            }
            #pragma unroll
            for (int st=4; st>=1; st>>=1)
                #pragma unroll
                for (int j=0;j<st;j++) kk8[j] = umax64(kk8[2*j],kk8[2*j+1]);
            unsigned hi  = (unsigned)(kk8[0]>>32);
            unsigned whi = __reduce_max_sync(FULLM, hi);
            unsigned cand= (hi==whi) ? (unsigned)kk8[0] : 0u;
            unsigned wlo = __reduce_max_sync(FULLM, cand);
            wkey = (((unsigned long long)whi)<<32) | wlo;
            wmaxdd = __uint_as_float(whi);
        }
        int par = it & 1;
        if (lane==0) s_key[par][wid] = wkey;       // cached when warp skipped
        __syncthreads();
        unsigned long long kk = s_key[par][lane & 7];
        unsigned hi2 = (unsigned)(kk>>32);
        unsigned bh  = __reduce_max_sync(FULLM, hi2);
        unsigned c2  = (hi2==bh) ? (unsigned)kk : 0u;
        unsigned bl  = __reduce_max_sync(FULLM, c2);
        f = 4095 - (int)(bl & 0xFFFu);
        cx=__ldg(X+f); cy=__ldg(X+NPT+f); cz=__ldg(X+2*NPT+f);   // broadcast L1 hit
    }
    __syncthreads();
    for (int i=t;i<3*NQ;i+=256){
        int c=i>>10, s=i&1023;
        out1[b*3072 + i] = X[c*NPT + g_fps[b*NQ+s]];
    }
}

// ---------------- ball query: packed f32x2 distance eval ------------------
__global__ void __launch_bounds__(256) bq_kernel(const float* __restrict__ xyz,
                                                 const float* __restrict__ out1)
{
    __shared__ unsigned ebuf[8*128];
    int b = blockIdx.x >> 5, qb = blockIdx.x & 31;
    const float* Xx = xyz + b*3*NPT;
    const float* Xy = Xx + NPT;
    const float* Xz = Xx + 2*NPT;
    int wid = threadIdx.x>>5, lane = threadIdx.x&31;
    unsigned lt = (1u<<lane)-1u;
    unsigned* wbuf = ebuf + wid*128;
    int s0 = qb*32 + wid*4;
    float cx[4],cy[4],cz[4]; int cnt[4]={0,0,0,0}; unsigned gtag[4];
    unsigned long long ncx[4],ncy[4],ncz[4];
    #pragma unroll
    for (int q=0;q<4;q++){
        int s = s0+q;
        cx[q]=__ldg(out1 + b*3072 + s);
        cy[q]=__ldg(out1 + b*3072 + 1024 + s);
        cz[q]=__ldg(out1 + b*3072 + 2048 + s);
        ncx[q]=pk2(-cx[q],-cx[q]); ncy[q]=pk2(-cy[q],-cy[q]); ncz[q]=pk2(-cz[q],-cz[q]);
        gtag[q]=(unsigned)(b*NQ+s)<<12;
    }
    int wn = 0;
    for (int bp=0; bp<NPT; bp+=128){
        if (cnt[0]>=NSAMP && cnt[1]>=NSAMP && cnt[2]>=NSAMP && cnt[3]>=NSAMP) break;
        int p = bp + lane*4;
        float4 fx = __ldg((const float4*)(Xx+p));
        float4 fy = __ldg((const float4*)(Xy+p));
        float4 fz = __ldg((const float4*)(Xz+p));
        unsigned long long pxa=pk2(fx.x,fx.y), pxb=pk2(fx.z,fx.w);
        unsigned long long pya=pk2(fy.x,fy.y), pyb=pk2(fy.z,fy.w);
        unsigned long long pza=pk2(fz.x,fz.y), pzb=pk2(fz.z,fz.w);
        #pragma unroll
        for (int q=0;q<4;q++){
            if (cnt[q]>=NSAMP) continue;          // warp-uniform
            unsigned long long dxa=add2(pxa,ncx[q]), dya=add2(pya,ncy[q]), dza=add2(pza,ncz[q]);
            unsigned long long dxb=add2(pxb,ncx[q]), dyb=add2(pyb,ncy[q]), dzb=add2(pzb,ncz[q]);
            unsigned long long sa=add2(add2(mul2(dxa,dxa),mul2(dya,dya)),mul2(dza,dza));
            unsigned long long sb=add2(add2(mul2(dxb,dxb),mul2(dyb,dyb)),mul2(dzb,dzb));
            float d0,d1,d2,d3; upk2(sa,d0,d1); upk2(sb,d2,d3);
            bool inb[4] = { d0<=0.04f, d1<=0.04f, d2<=0.04f, d3<=0.04f };
            unsigned m[4];
            #pragma unroll
            for (int j=0;j<4;j++) m[j] = __ballot_sync(FULLM, inb[j]);
            int tot = __popc(m[0])+__popc(m[1])+__popc(m[2])+__popc(m[3]);
            if (!tot) continue;                    // warp-uniform
            if (cnt[q] + tot <= NSAMP){
                int off = wn;                      // order irrelevant downstream
                #pragma unroll
                for (int j=0;j<4;j++){
                    if (inb[j]) wbuf[off + __popc(m[j]&lt)] = gtag[q] | (unsigned)(p+j);
                    off += __popc(m[j]);
                }
                wn += tot; cnt[q] += tot;
            } else {
                // rare: crossing NSAMP — redo this 128-chunk in index order
                for (int sub=0; sub<4 && cnt[q]<NSAMP; ++sub){
                    int pp = bp + sub*32 + lane;
                    float dx=__ldg(Xx+pp)-cx[q], dy=__ldg(Xy+pp)-cy[q], dz=__ldg(Xz+pp)-cz[q];
                    float dsq = __fadd_rn(__fadd_rn(__fmul_rn(dx,dx),__fmul_rn(dy,dy)),__fmul_rn(dz,dz));
                    bool in = (dsq <= 0.04f);
                    unsigned mask = __ballot_sync(FULLM, in);
                    int pc = __popc(mask);
                    int take = min(pc, NSAMP-cnt[q]);
                    if (in){
                        int pos = __popc(mask & lt);
                        if (pos < take) wbuf[wn+pos] = gtag[q] | (unsigned)pp;
                    }
                    wn += take; cnt[q] += take;
                }
            }
        }
    }
    int gb = 0;
    if (lane==0) gb = atomicAdd(&g_ecnt, wn);
    gb = __shfl_sync(FULLM, gb, 0);
    for (int i=lane;i<wn;i+=32) g_ent[gb+i] = wbuf[i];
}

// ---------------- fused 3-layer MLP + max scatter (4 CTAs/SM) -------------
__global__ void __launch_bounds__(256,4) mlp_kernel(const float* __restrict__ xyz,
                                                    float* __restrict__ out2)
{
    extern __shared__ float sm[];
    float* sX  = sm;            // 67*64 = 4288
    float* sH  = sm + 4288;     // 64*64 = 4096
    float* sB0 = sm + 8384;
    float* sB1 = sm + 8448;
    float* sB2 = sm + 8512;     // total 8640 floats = 34560 B
    int t = threadIdx.x;
    if (t<64){ sB0[t]=g_B0[t]; sB1[t]=g_B1[t]; }
    if (t<128) sB2[t]=g_B2[t];
    int E = g_ecnt;
    int tiles = (E+63)>>6;
    int tx = t&15, ty = t>>4;
    int* outI = (int*)out2;
    int le = t>>2, sub = t&3;
    for (int tb = blockIdx.x; tb < tiles; tb += gridDim.x){
        int tbase = tb<<6;
        __syncthreads();
        {   // gather 67-channel input (4 threads / entry, contiguous pts rows)
            int ge = tbase + le;
            unsigned raw = g_ent[ge < E ? ge : 0] & 0x3FFFFFFu;
            int p = raw & 4095; int g = raw >> 12; int bb = g >> 10;
            const float* pt = g_ptsT + ((size_t)(bb*NPT) + p)*64 + sub*16;
            #pragma unroll
            for (int k=0;k<4;k++){
                float4 v = __ldg((const float4*)(pt + k*4));
                int c = 3 + sub*16 + k*4;
                sX[(c  )*64+le] = v.x;
                sX[(c+1)*64+le] = v.y;
                sX[(c+2)*64+le] = v.z;
                sX[(c+3)*64+le] = v.w;
            }
            if (sub == 0){
                int ci = g_fps[g];
                const float* xc = xyz + (size_t)(bb*3)*NPT;
                #pragma unroll
                for (int c=0;c<3;c++)
                    sX[c*64+le] = __ldg(xc + c*NPT + p) - __ldg(xc + c*NPT + ci);
            }
        }
        __syncthreads();
        // ---- layer 0: 67 -> 64 ----
        float acc[4][4];
        #pragma unroll
        for (int j=0;j<4;j++){ float bb=sB0[ty*4+j];
            #pragma unroll
            for (int i=0;i<4;i++) acc[i][j]=bb; }
        #pragma unroll 4
        for (int k=0;k<67;k++){
            float4 xv = *(const float4*)&sX[k*64+tx*4];
            float4 wv = __ldg((const float4*)&g_W0[k*64+ty*4]);
            float xr[4]={xv.x,xv.y,xv.z,xv.w};
            float wr[4]={wv.x,wv.y,wv.z,wv.w};
            #pragma unroll
            for (int i=0;i<4;i++)
                #pragma unroll
                for (int j=0;j<4;j++) acc[i][j] = fmaf(xr[i],wr[j],acc[i][j]);
        }
        #pragma unroll
        for (int j=0;j<4;j++){
            float4 hv = make_float4(fmaxf(acc[0][j],0.f),fmaxf(acc[1][j],0.f),
                                    fmaxf(acc[2][j],0.f),fmaxf(acc[3][j],0.f));
            *(float4*)&sH[(ty*4+j)*64 + tx*4] = hv;
        }
        __syncthreads();
        // ---- layer 1: 64 -> 64 ----
        #pragma unroll
        for (int j=0;j<4;j++){ float bb=sB1[ty*4+j];
            #pragma unroll
            for (int i=0;i<4;i++) acc[i][j]=bb; }
        #pragma unroll 4
        for (int k=0;k<64;k++){
            float4 xv = *(const float4*)&sH[k*64+tx*4];
            float4 wv = __ldg((const float4*)&g_W1[k*64+ty*4]);
            float xr[4]={xv.x,xv.y,xv.z,xv.w};
            float wr[4]={wv.x,wv.y,wv.z,wv.w};
            #pragma unroll
            for (int i=0;i<4;i++)
                #pragma unroll
                for (int j=0;j<4;j++) acc[i][j] = fmaf(xr[i],wr[j],acc[i][j]);
        }
        #pragma unroll
        for (int j=0;j<4;j++){
            float4 hv = make_float4(fmaxf(acc[0][j],0.f),fmaxf(acc[1][j],0.f),
                                    fmaxf(acc[2][j],0.f),fmaxf(acc[3][j],0.f));
            *(float4*)&sX[(ty*4+j)*64 + tx*4] = hv;
        }
        __syncthreads();
        // ---- layer 2: 64 -> 128, two 4-wide halves (reg pressure) ----
        unsigned gid[4];
        #pragma unroll
        for (int i=0;i<4;i++){
            int ge = tbase + tx*4 + i;
            gid[i] = (ge < E) ? ((g_ent[ge] >> 12) & 0x3FFFu) : 0xFFFFFFFFu;
        }
        #pragma unroll
        for (int h=0; h<2; h++){
            #pragma unroll
            for (int j=0;j<4;j++){ float bb=sB2[ty*8+h*4+j];
                #pragma unroll
                for (int i=0;i<4;i++) acc[i][j]=bb; }
            #pragma unroll 4
            for (int k=0;k<64;k++){
                float4 xv = *(const float4*)&sX[k*64+tx*4];
                float4 wv = __ldg((const float4*)&g_W2[k*128+ty*8+h*4]);
                float xr[4]={xv.x,xv.y,xv.z,xv.w};
                float wr[4]={wv.x,wv.y,wv.z,wv.w};
                #pragma unroll
                for (int i=0;i<4;i++)
                    #pragma unroll
                    for (int j=0;j<4;j++) acc[i][j]=fmaf(xr[i],wr[j],acc[i][j]);
            }
            #pragma unroll
            for (int i=0;i<4;i++){
                if (gid[i]==0xFFFFFFFFu) continue;
                if (i>0 && gid[i]==gid[i-1]) continue;   // merged into earlier head
                float mv[4];
                #pragma unroll
                for (int j=0;j<4;j++) mv[j]=acc[i][j];
                #pragma unroll
                for (int i2=1;i2<4;i2++){
                    if (i+i2<4 && gid[i+i2]==gid[i]){
                        #pragma unroll
                        for (int j=0;j<4;j++) mv[j]=fmaxf(mv[j],acc[i+i2][j]);
                    }
                }
                int bb = gid[i]>>10, s = gid[i]&1023;
                int* po = outI + (bb*128 + ty*8 + h*4)*NQ + s;
                #pragma unroll
                for (int j=0;j<4;j++)
                    atomicMax(po + j*NQ, __float_as_int(fmaxf(mv[j],0.f)));
            }
        }
    }
}

extern "C" void kernel_launch(void* const* d_in, const int* in_sizes, int n_in,
                              void* d_out, int out_size)
{
    const float* xyz = (const float*)d_in[0];
    const float* pts = (const float*)d_in[1];
    float* out1 = (float*)d_out;
    float* out2 = out1 + OUT1SZ;

    prep_kernel<<<2048,256>>>(out2, pts, xyz,
        (const float*)d_in[2],(const float*)d_in[3],(const float*)d_in[4],
        (const float*)d_in[5],(const float*)d_in[6],(const float*)d_in[7],
        (const float*)d_in[8],(const float*)d_in[9],(const float*)d_in[10],
        (const float*)d_in[11],(const float*)d_in[12],(const float*)d_in[13],
        (const float*)d_in[14],(const float*)d_in[15],(const float*)d_in[16],
        (const float*)d_in[17],(const float*)d_in[18],(const float*)d_in[19]);
    fps_kernel<<<16,256>>>(xyz, out1);
    bq_kernel<<<512,256>>>(xyz, out1);
    mlp_kernel<<<592,256,34560>>>(xyz, out2);
}

// round 16
// speedup vs baseline: 1.0891x; 1.0891x over previous
#include <cuda_runtime.h>

#define NBATCH 16
#define NPT    4096
#define NQ     1024
#define NSAMP  32
#define OUT1SZ (NBATCH*3*NQ)
#define OUT2SZ (NBATCH*128*NQ)
#define MAXE   (NBATCH*NQ*NSAMP + 64)
#define FULLM  0xffffffffu

__device__ int      g_fps[NBATCH*NQ];
__device__ unsigned g_ent[MAXE];
__device__ int      g_ecnt;
__device__ float    g_ptsT[NBATCH*NPT*64];   // [b][p][c] transposed points
__device__ float    g_W0[67*64], g_B0[64];
__device__ float    g_W1[64*64], g_B1[64];
__device__ float    g_W2[64*128], g_B2[128];

// ---- f32x2 packed helpers: two independent .rn fp32 ops per instruction --
__device__ __forceinline__ unsigned long long pk2(float a, float b){
    unsigned long long r; asm("mov.b64 %0,{%1,%2};":"=l"(r):"f"(a),"f"(b)); return r;
}
__device__ __forceinline__ void upk2(unsigned long long v, float&a, float&b){
    asm("mov.b64 {%0,%1},%2;":"=f"(a),"=f"(b):"l"(v));
}
__device__ __forceinline__ unsigned long long add2(unsigned long long a, unsigned long long b){
    unsigned long long r; asm("add.rn.f32x2 %0,%1,%2;":"=l"(r):"l"(a),"l"(b)); return r;
}
__device__ __forceinline__ unsigned long long mul2(unsigned long long a, unsigned long long b){
    unsigned long long r; asm("mul.rn.f32x2 %0,%1,%2;":"=l"(r):"l"(a),"l"(b)); return r;
}

// ---------------- prep: zero out2 + fold BN + transpose pts ---------------
__global__ void __launch_bounds__(256) prep_kernel(float* __restrict__ out2,
    const float* __restrict__ pts,
    const float* w0,const float* b0,const float* g0,const float* be0,const float* m0,const float* v0,
    const float* w1,const float* b1,const float* g1,const float* be1,const float* m1,const float* v1,
    const float* w2,const float* b2,const float* g2,const float* be2,const float* m2,const float* v2)
{
    __shared__ float tile[64][65];
    int idx = blockIdx.x*blockDim.x + threadIdx.x;
    if (idx < OUT2SZ/4) ((float4*)out2)[idx] = make_float4(0.f,0.f,0.f,0.f);
    if (blockIdx.x == 0) {
        int t = threadIdx.x;
        if (t == 0) g_ecnt = 0;
        for (int i=t;i<67*64;i+=blockDim.x){int c=i>>6,o=i&63;float s=g0[o]*rsqrtf(v0[o]+1e-5f);g_W0[i]=w0[o*67+c]*s;}
        for (int i=t;i<64*64;i+=blockDim.x){int c=i>>6,o=i&63;float s=g1[o]*rsqrtf(v1[o]+1e-5f);g_W1[i]=w1[o*64+c]*s;}
        for (int i=t;i<64*128;i+=blockDim.x){int k=i>>7,o=i&127;float s=g2[o]*rsqrtf(v2[o]+1e-5f);g_W2[i]=w2[o*64+k]*s;}
        if (t<64){float s=g0[t]*rsqrtf(v0[t]+1e-5f);g_B0[t]=(b0[t]-m0[t])*s+be0[t];}
        if (t<64){float s=g1[t]*rsqrtf(v1[t]+1e-5f);g_B1[t]=(b1[t]-m1[t])*s+be1[t];}
        if (t<128){float s=g2[t]*rsqrtf(v2[t]+1e-5f);g_B2[t]=(b2[t]-m2[t])*s+be2[t];}
    }
    // transpose: CTAs 0..1023 each handle one [64ch x 64pt] tile
    if (blockIdx.x < 1024){
        int b = blockIdx.x >> 6, pt = blockIdx.x & 63;
        int p0 = pt*64;
        const float* src = pts + (size_t)b*64*NPT;
        for (int i=threadIdx.x; i<64*64; i+=256){
            int c = i>>6, pl = i&63;
            tile[c][pl] = src[(size_t)c*NPT + p0 + pl];
        }
        __syncthreads();
        float* dst = g_ptsT + ((size_t)b*NPT + p0)*64;
        for (int i=threadIdx.x; i<64*64; i+=256){
            int pl = i>>6, c = i&63;
            dst[(size_t)pl*64 + c] = tile[c][pl];
        }
    }
}

// ---------------- FPS: 256 thr/CTA, 16 pts/thread, stable tree argmax -----
__global__ void __launch_bounds__(256,1) fps_kernel(const float* __restrict__ xyz,
                                                    float* __restrict__ out1)
{
    __shared__ unsigned s_v[2][8], s_ix[2][8];
    int b = blockIdx.x, t = threadIdx.x;
    int lane = t & 31, wid = t >> 5;
    const float* X = xyz + b*3*NPT;
    int base = t*16;
    float px[16],py[16],pz[16],dd[16];
    #pragma unroll
    for (int q=0;q<4;q++){
        float4 a = *(const float4*)(X + base + q*4);
        float4 bv = *(const float4*)(X + NPT + base + q*4);
        float4 c = *(const float4*)(X + 2*NPT + base + q*4);
        px[q*4]=a.x;px[q*4+1]=a.y;px[q*4+2]=a.z;px[q*4+3]=a.w;
        py[q*4]=bv.x;py[q*4+1]=bv.y;py[q*4+2]=bv.z;py[q*4+3]=bv.w;
        pz[q*4]=c.x;pz[q*4+1]=c.y;pz[q*4+2]=c.z;pz[q*4+3]=c.w;
    }
    unsigned long long px2[8],py2[8],pz2[8];
    #pragma unroll
    for (int p=0;p<8;p++){ px2[p]=pk2(px[2*p],px[2*p+1]); py2[p]=pk2(py[2*p],py[2*p+1]); pz2[p]=pk2(pz[2*p],pz[2*p+1]); }
    #pragma unroll
    for (int j=0;j<16;j++) dd[j]=1e10f;
    int f = 0;
    float cx=__ldg(X), cy=__ldg(X+NPT), cz=__ldg(X+2*NPT);
    for (int it=0; it<NQ; ++it) {
        if (t == 0) g_fps[b*NQ+it] = f;
        unsigned long long ncx=pk2(-cx,-cx), ncy=pk2(-cy,-cy), ncz=pk2(-cz,-cz);
        #pragma unroll
        for (int p=0;p<8;p++){
            // (px-cx)^2+(py-cy)^2+(pz-cz)^2, each op .rn, left-assoc (matches XLA)
            unsigned long long dx=add2(px2[p],ncx), dy=add2(py2[p],ncy), dz=add2(pz2[p],ncz);
            unsigned long long d2=add2(add2(mul2(dx,dx),mul2(dy,dy)),mul2(dz,dz));
            float dlo,dhi; upk2(d2,dlo,dhi);
            dd[2*p]   = fminf(dd[2*p],   dlo);
            dd[2*p+1] = fminf(dd[2*p+1], dhi);
        }
        // stable adjacent-pair argmax tree (ties -> lowest index, matches ref)
        float tv[8]; int tj[8];
        #pragma unroll
        for (int j=0;j<8;j++){
            bool c = dd[2*j+1] > dd[2*j];
            tv[j] = c ? dd[2*j+1] : dd[2*j];
            tj[j] = c ? 2*j+1 : 2*j;
        }
        #pragma unroll
        for (int st=4; st>=1; st>>=1){
            #pragma unroll
            for (int j=0;j<st;j++){
                bool c = tv[2*j+1] > tv[2*j];
                tv[j] = c ? tv[2*j+1] : tv[2*j];
                tj[j] = c ? tj[2*j+1] : tj[2*j];
            }
        }
        float best = tv[0]; int bidx = base + tj[0];
        unsigned db   = __float_as_uint(best);        // >=0: uint order == float order
        unsigned wmax = __reduce_max_sync(FULLM, db);
        unsigned mk   = __ballot_sync(FULLM, db==wmax);
        int src = __ffs(mk)-1;                         // lowest lane = lowest index
        int par = it & 1;
        if (db==wmax && lane==src){                    // winner lane writes directly
            s_v[par][wid]=wmax; s_ix[par][wid]=(unsigned)bidx;
        }
        __syncthreads();
        unsigned vm   = s_v[par][lane & 7];
        unsigned bmax = __reduce_max_sync(FULLM, vm);
        unsigned mk2  = __ballot_sync(FULLM, vm==bmax);
        int src2 = __ffs(mk2)-1;                       // lowest warp = lowest index
        f = (int)s_ix[par][src2];
        cx=__ldg(X+f); cy=__ldg(X+NPT+f); cz=__ldg(X+2*NPT+f);   // broadcast L1 hit
    }
    __syncthreads();
    for (int i=t;i<3*NQ;i+=256){
        int c=i>>10, s=i&1023;
        out1[b*3072 + i] = X[c*NPT + g_fps[b*NQ+s]];
    }
}

// ---------------- ball query: packed f32x2 distance eval ------------------
__global__ void __launch_bounds__(256) bq_kernel(const float* __restrict__ xyz,
                                                 const float* __restrict__ out1)
{
    __shared__ unsigned ebuf[8*128];
    int b = blockIdx.x >> 5, qb = blockIdx.x & 31;
    const float* Xx = xyz + b*3*NPT;
    const float* Xy = Xx + NPT;
    const float* Xz = Xx + 2*NPT;
    int wid = threadIdx.x>>5, lane = threadIdx.x&31;
    unsigned lt = (1u<<lane)-1u;
    unsigned* wbuf = ebuf + wid*128;
    int s0 = qb*32 + wid*4;
    float cx[4],cy[4],cz[4]; int cnt[4]={0,0,0,0}; unsigned gtag[4];
    unsigned long long ncx[4],ncy[4],ncz[4];
    #pragma unroll
    for (int q=0;q<4;q++){
        int s = s0+q;
        cx[q]=__ldg(out1 + b*3072 + s);
        cy[q]=__ldg(out1 + b*3072 + 1024 + s);
        cz[q]=__ldg(out1 + b*3072 + 2048 + s);
        ncx[q]=pk2(-cx[q],-cx[q]); ncy[q]=pk2(-cy[q],-cy[q]); ncz[q]=pk2(-cz[q],-cz[q]);
        gtag[q]=(unsigned)(b*NQ+s)<<12;
    }
    int wn = 0;
    for (int bp=0; bp<NPT; bp+=128){
        if (cnt[0]>=NSAMP && cnt[1]>=NSAMP && cnt[2]>=NSAMP && cnt[3]>=NSAMP) break;
        int p = bp + lane*4;
        float4 fx = __ldg((const float4*)(Xx+p));
        float4 fy = __ldg((const float4*)(Xy+p));
        float4 fz = __ldg((const float4*)(Xz+p));
        unsigned long long pxa=pk2(fx.x,fx.y), pxb=pk2(fx.z,fx.w);
        unsigned long long pya=pk2(fy.x,fy.y), pyb=pk2(fy.z,fy.w);
        unsigned long long pza=pk2(fz.x,fz.y), pzb=pk2(fz.z,fz.w);
        #pragma unroll
        for (int q=0;q<4;q++){
            if (cnt[q]>=NSAMP) continue;          // warp-uniform
            // packed distance eval: bitwise identical to scalar .rn sequence
            unsigned long long dxa=add2(pxa,ncx[q]), dya=add2(pya,ncy[q]), dza=add2(pza,ncz[q]);
            unsigned long long dxb=add2(pxb,ncx[q]), dyb=add2(pyb,ncy[q]), dzb=add2(pzb,ncz[q]);
            unsigned long long sa=add2(add2(mul2(dxa,dxa),mul2(dya,dya)),mul2(dza,dza));
            unsigned long long sb=add2(add2(mul2(dxb,dxb),mul2(dyb,dyb)),mul2(dzb,dzb));
            float d0,d1,d2,d3; upk2(sa,d0,d1); upk2(sb,d2,d3);
            bool inb[4] = { d0<=0.04f, d1<=0.04f, d2<=0.04f, d3<=0.04f };
            unsigned m[4];
            #pragma unroll
            for (int j=0;j<4;j++) m[j] = __ballot_sync(FULLM, inb[j]);
            int tot = __popc(m[0])+__popc(m[1])+__popc(m[2])+__popc(m[3]);
            if (!tot) continue;                    // warp-uniform
            if (cnt[q] + tot <= NSAMP){
                int off = wn;                      // order irrelevant downstream
                #pragma unroll
                for (int j=0;j<4;j++){
                    if (inb[j]) wbuf[off + __popc(m[j]&lt)] = gtag[q] | (unsigned)(p+j);
                    off += __popc(m[j]);
                }
                wn += tot; cnt[q] += tot;
            } else {
                // rare: crossing NSAMP — redo this 128-chunk in index order
                for (int sub=0; sub<4 && cnt[q]<NSAMP; ++sub){
                    int pp = bp + sub*32 + lane;
                    float dx=__ldg(Xx+pp)-cx[q], dy=__ldg(Xy+pp)-cy[q], dz=__ldg(Xz+pp)-cz[q];
                    float dsq = __fadd_rn(__fadd_rn(__fmul_rn(dx,dx),__fmul_rn(dy,dy)),__fmul_rn(dz,dz));
                    bool in = (dsq <= 0.04f);
                    unsigned mask = __ballot_sync(FULLM, in);
                    int pc = __popc(mask);
                    int take = min(pc, NSAMP-cnt[q]);
                    if (in){
                        int pos = __popc(mask & lt);
                        if (pos < take) wbuf[wn+pos] = gtag[q] | (unsigned)pp;
                    }
                    wn += take; cnt[q] += take;
                }
            }
        }
    }
    int gb = 0;
    if (lane==0) gb = atomicAdd(&g_ecnt, wn);
    gb = __shfl_sync(FULLM, gb, 0);
    for (int i=lane;i<wn;i+=32) g_ent[gb+i] = wbuf[i];
}

// ---------------- fused 3-layer MLP + max scatter (4 CTAs/SM) -------------
__global__ void __launch_bounds__(256,4) mlp_kernel(const float* __restrict__ xyz,
                                                    float* __restrict__ out2)
{
    extern __shared__ float sm[];
    float* sX  = sm;            // 67*64 = 4288
    float* sH  = sm + 4288;     // 64*64 = 4096
    float* sB0 = sm + 8384;
    float* sB1 = sm + 8448;
    float* sB2 = sm + 8512;     // total 8640 floats = 34560 B
    int t = threadIdx.x;
    if (t<64){ sB0[t]=g_B0[t]; sB1[t]=g_B1[t]; }
    if (t<128) sB2[t]=g_B2[t];
    int E = g_ecnt;
    int tiles = (E+63)>>6;
    int tx = t&15, ty = t>>4;
    int* outI = (int*)out2;
    int le = t>>2, sub = t&3;
    for (int tb = blockIdx.x; tb < tiles; tb += gridDim.x){
        int tbase = tb<<6;
        __syncthreads();
        {   // gather 67-channel input (4 threads / entry, contiguous pts rows)
            int ge = tbase + le;
            unsigned raw = g_ent[ge < E ? ge : 0] & 0x3FFFFFFu;
            int p = raw & 4095; int g = raw >> 12; int bb = g >> 10;
            const float* pt = g_ptsT + ((size_t)(bb*NPT) + p)*64 + sub*16;
            #pragma unroll
            for (int k=0;k<4;k++){
                float4 v = __ldg((const float4*)(pt + k*4));
                int c = 3 + sub*16 + k*4;
                sX[(c  )*64+le] = v.x;
                sX[(c+1)*64+le] = v.y;
                sX[(c+2)*64+le] = v.z;
                sX[(c+3)*64+le] = v.w;
            }
            if (sub == 0){
                int ci = g_fps[g];
                const float* xc = xyz + (size_t)(bb*3)*NPT;
                #pragma unroll
                for (int c=0;c<3;c++)
                    sX[c*64+le] = __ldg(xc + c*NPT + p) - __ldg(xc + c*NPT + ci);
            }
        }
        __syncthreads();
        // ---- layer 0: 67 -> 64 ----
        float acc[4][4];
        #pragma unroll
        for (int j=0;j<4;j++){ float bb=sB0[ty*4+j];
            #pragma unroll
            for (int i=0;i<4;i++) acc[i][j]=bb; }
        #pragma unroll 4
        for (int k=0;k<67;k++){
            float4 xv = *(const float4*)&sX[k*64+tx*4];
            float4 wv = __ldg((const float4*)&g_W0[k*64+ty*4]);
            float xr[4]={xv.x,xv.y,xv.z,xv.w};
            float wr[4]={wv.x,wv.y,wv.z,wv.w};
            #pragma unroll
            for (int i=0;i<4;i++)
                #pragma unroll
                for (int j=0;j<4;j++) acc[i][j] = fmaf(xr[i],wr[j],acc[i][j]);
        }
        #pragma unroll
        for (int j=0;j<4;j++){
            float4 hv = make_float4(fmaxf(acc[0][j],0.f),fmaxf(acc[1][j],0.f),
                                    fmaxf(acc[2][j],0.f),fmaxf(acc[3][j],0.f));
            *(float4*)&sH[(ty*4+j)*64 + tx*4] = hv;
        }
        __syncthreads();
        // ---- layer 1: 64 -> 64 ----
        #pragma unroll
        for (int j=0;j<4;j++){ float bb=sB1[ty*4+j];
            #pragma unroll
            for (int i=0;i<4;i++) acc[i][j]=bb; }
        #pragma unroll 4
        for (int k=0;k<64;k++){
            float4 xv = *(const float4*)&sH[k*64+tx*4];
            float4 wv = __ldg((const float4*)&g_W1[k*64+ty*4]);
            float xr[4]={xv.x,xv.y,xv.z,xv.w};
            float wr[4]={wv.x,wv.y,wv.z,wv.w};
            #pragma unroll
            for (int i=0;i<4;i++)
                #pragma unroll
                for (int j=0;j<4;j++) acc[i][j] = fmaf(xr[i],wr[j],acc[i][j]);
        }
        #pragma unroll
        for (int j=0;j<4;j++){
            float4 hv = make_float4(fmaxf(acc[0][j],0.f),fmaxf(acc[1][j],0.f),
                                    fmaxf(acc[2][j],0.f),fmaxf(acc[3][j],0.f));
            *(float4*)&sX[(ty*4+j)*64 + tx*4] = hv;
        }
        __syncthreads();
        // ---- layer 2: 64 -> 128, two 4-wide halves (reg pressure) ----
        unsigned gid[4];
        #pragma unroll
        for (int i=0;i<4;i++){
            int ge = tbase + tx*4 + i;
            gid[i] = (ge < E) ? ((g_ent[ge] >> 12) & 0x3FFFu) : 0xFFFFFFFFu;
        }
        #pragma unroll
        for (int h=0; h<2; h++){
            #pragma unroll
            for (int j=0;j<4;j++){ float bb=sB2[ty*8+h*4+j];
                #pragma unroll
                for (int i=0;i<4;i++) acc[i][j]=bb; }
            #pragma unroll 4
            for (int k=0;k<64;k++){
                float4 xv = *(const float4*)&sX[k*64+tx*4];
                float4 wv = __ldg((const float4*)&g_W2[k*128+ty*8+h*4]);
                float xr[4]={xv.x,xv.y,xv.z,xv.w};
                float wr[4]={wv.x,wv.y,wv.z,wv.w};
                #pragma unroll
                for (int i=0;i<4;i++)
                    #pragma unroll
                    for (int j=0;j<4;j++) acc[i][j]=fmaf(xr[i],wr[j],acc[i][j]);
            }
            #pragma unroll
            for (int i=0;i<4;i++){
                if (gid[i]==0xFFFFFFFFu) continue;
                if (i>0 && gid[i]==gid[i-1]) continue;   // merged into earlier head
                float mv[4];
                #pragma unroll
                for (int j=0;j<4;j++) mv[j]=acc[i][j];
                #pragma unroll
                for (int i2=1;i2<4;i2++){
                    if (i+i2<4 && gid[i+i2]==gid[i]){
                        #pragma unroll
                        for (int j=0;j<4;j++) mv[j]=fmaxf(mv[j],acc[i+i2][j]);
                    }
                }
                int bb = gid[i]>>10, s = gid[i]&1023;
                int* po = outI + (bb*128 + ty*8 + h*4)*NQ + s;
                #pragma unroll
                for (int j=0;j<4;j++)
                    atomicMax(po + j*NQ, __float_as_int(fmaxf(mv[j],0.f)));
            }
        }
    }
}

extern "C" void kernel_launch(void* const* d_in, const int* in_sizes, int n_in,
                              void* d_out, int out_size)
{
    const float* xyz = (const float*)d_in[0];
    const float* pts = (const float*)d_in[1];
    float* out1 = (float*)d_out;
    float* out2 = out1 + OUT1SZ;

    prep_kernel<<<2048,256>>>(out2, pts,
        (const float*)d_in[2],(const float*)d_in[3],(const float*)d_in[4],
        (const float*)d_in[5],(const float*)d_in[6],(const float*)d_in[7],
        (const float*)d_in[8],(const float*)d_in[9],(const float*)d_in[10],
        (const float*)d_in[11],(const float*)d_in[12],(const float*)d_in[13],
        (const float*)d_in[14],(const float*)d_in[15],(const float*)d_in[16],
        (const float*)d_in[17],(const float*)d_in[18],(const float*)d_in[19]);
    fps_kernel<<<16,256>>>(xyz, out1);
    bq_kernel<<<512,256>>>(xyz, out1);
    mlp_kernel<<<592,256,34560>>>(xyz, out2);
}

// round 17
// speedup vs baseline: 1.1098x; 1.0190x over previous
#include <cuda_runtime.h>
#include <cuda_pipeline.h>

#define NBATCH 16
#define NPT    4096
#define NQ     1024
#define NSAMP  32
#define OUT1SZ (NBATCH*3*NQ)
#define OUT2SZ (NBATCH*128*NQ)
#define MAXE   (NBATCH*NQ*NSAMP + 64)
#define FULLM  0xffffffffu

__device__ int      g_fps[NBATCH*NQ];
__device__ unsigned g_ent[MAXE];
__device__ int      g_ecnt;
__device__ float    g_ptsT[NBATCH*NPT*64];   // [b][p][c] transposed points
__device__ float    g_W0[67*64], g_B0[64];   // W0 rows: 0..63 = pts ch, 64..66 = xyz ch
__device__ float    g_W1[64*64], g_B1[64];
__device__ float    g_W2[64*128], g_B2[128];

// ---- f32x2 packed helpers: two independent .rn fp32 ops per instruction --
__device__ __forceinline__ unsigned long long pk2(float a, float b){
    unsigned long long r; asm("mov.b64 %0,{%1,%2};":"=l"(r):"f"(a),"f"(b)); return r;
}
__device__ __forceinline__ void upk2(unsigned long long v, float&a, float&b){
    asm("mov.b64 {%0,%1},%2;":"=f"(a),"=f"(b):"l"(v));
}
__device__ __forceinline__ unsigned long long add2(unsigned long long a, unsigned long long b){
    unsigned long long r; asm("add.rn.f32x2 %0,%1,%2;":"=l"(r):"l"(a),"l"(b)); return r;
}
__device__ __forceinline__ unsigned long long mul2(unsigned long long a, unsigned long long b){
    unsigned long long r; asm("mul.rn.f32x2 %0,%1,%2;":"=l"(r):"l"(a),"l"(b)); return r;
}

// ---------------- prep: zero out2 + fold BN + transpose pts ---------------
__global__ void __launch_bounds__(256) prep_kernel(float* __restrict__ out2,
    const float* __restrict__ pts,
    const float* w0,const float* b0,const float* g0,const float* be0,const float* m0,const float* v0,
    const float* w1,const float* b1,const float* g1,const float* be1,const float* m1,const float* v1,
    const float* w2,const float* b2,const float* g2,const float* be2,const float* m2,const float* v2)
{
    __shared__ float tile[64][65];
    int idx = blockIdx.x*blockDim.x + threadIdx.x;
    if (idx < OUT2SZ/4) ((float4*)out2)[idx] = make_float4(0.f,0.f,0.f,0.f);
    if (blockIdx.x == 0) {
        int t = threadIdx.x;
        if (t == 0) g_ecnt = 0;
        // W0 with permuted rows: newr 0..63 <- old channel newr+3 (pts), 64..66 <- xyz 0..2
        for (int i=t;i<67*64;i+=blockDim.x){
            int nr=i>>6,o=i&63; int oc = (nr<64)? nr+3 : nr-64;
            float s=g0[o]*rsqrtf(v0[o]+1e-5f);
            g_W0[i]=w0[o*67+oc]*s;
        }
        for (int i=t;i<64*64;i+=blockDim.x){int c=i>>6,o=i&63;float s=g1[o]*rsqrtf(v1[o]+1e-5f);g_W1[i]=w1[o*64+c]*s;}
        for (int i=t;i<64*128;i+=blockDim.x){int k=i>>7,o=i&127;float s=g2[o]*rsqrtf(v2[o]+1e-5f);g_W2[i]=w2[o*64+k]*s;}
        if (t<64){float s=g0[t]*rsqrtf(v0[t]+1e-5f);g_B0[t]=(b0[t]-m0[t])*s+be0[t];}
        if (t<64){float s=g1[t]*rsqrtf(v1[t]+1e-5f);g_B1[t]=(b1[t]-m1[t])*s+be1[t];}
        if (t<128){float s=g2[t]*rsqrtf(v2[t]+1e-5f);g_B2[t]=(b2[t]-m2[t])*s+be2[t];}
    }
    // transpose: CTAs 0..1023 each handle one [64ch x 64pt] tile
    if (blockIdx.x < 1024){
        int b = blockIdx.x >> 6, pt = blockIdx.x & 63;
        int p0 = pt*64;
        const float* src = pts + (size_t)b*64*NPT;
        for (int i=threadIdx.x; i<64*64; i+=256){
            int c = i>>6, pl = i&63;
            tile[c][pl] = src[(size_t)c*NPT + p0 + pl];
        }
        __syncthreads();
        float* dst = g_ptsT + ((size_t)b*NPT + p0)*64;
        for (int i=threadIdx.x; i<64*64; i+=256){
            int pl = i>>6, c = i&63;
            dst[(size_t)pl*64 + c] = tile[c][pl];
        }
    }
}

// ---------------- FPS: 256 thr/CTA, 16 pts/thread, stable tree argmax -----
__global__ void __launch_bounds__(256,1) fps_kernel(const float* __restrict__ xyz,
                                                    float* __restrict__ out1)
{
    __shared__ unsigned s_v[2][8], s_ix[2][8];
    int b = blockIdx.x, t = threadIdx.x;
    int lane = t & 31, wid = t >> 5;
    const float* X = xyz + b*3*NPT;
    int base = t*16;
    float px[16],py[16],pz[16],dd[16];
    #pragma unroll
    for (int q=0;q<4;q++){
        float4 a = *(const float4*)(X + base + q*4);
        float4 bv = *(const float4*)(X + NPT + base + q*4);
        float4 c = *(const float4*)(X + 2*NPT + base + q*4);
        px[q*4]=a.x;px[q*4+1]=a.y;px[q*4+2]=a.z;px[q*4+3]=a.w;
        py[q*4]=bv.x;py[q*4+1]=bv.y;py[q*4+2]=bv.z;py[q*4+3]=bv.w;
        pz[q*4]=c.x;pz[q*4+1]=c.y;pz[q*4+2]=c.z;pz[q*4+3]=c.w;
    }
    unsigned long long px2[8],py2[8],pz2[8];
    #pragma unroll
    for (int p=0;p<8;p++){ px2[p]=pk2(px[2*p],px[2*p+1]); py2[p]=pk2(py[2*p],py[2*p+1]); pz2[p]=pk2(pz[2*p],pz[2*p+1]); }
    #pragma unroll
    for (int j=0;j<16;j++) dd[j]=1e10f;
    int f = 0;
    float cx=__ldg(X), cy=__ldg(X+NPT), cz=__ldg(X+2*NPT);
    for (int it=0; it<NQ; ++it) {
        if (t == 0) g_fps[b*NQ+it] = f;
        unsigned long long ncx=pk2(-cx,-cx), ncy=pk2(-cy,-cy), ncz=pk2(-cz,-cz);
        #pragma unroll
        for (int p=0;p<8;p++){
            // (px-cx)^2+(py-cy)^2+(pz-cz)^2, each op .rn, left-assoc (matches XLA)
            unsigned long long dx=add2(px2[p],ncx), dy=add2(py2[p],ncy), dz=add2(pz2[p],ncz);
            unsigned long long d2=add2(add2(mul2(dx,dx),mul2(dy,dy)),mul2(dz,dz));
            float dlo,dhi; upk2(d2,dlo,dhi);
            dd[2*p]   = fminf(dd[2*p],   dlo);
            dd[2*p+1] = fminf(dd[2*p+1], dhi);
        }
        // stable adjacent-pair argmax tree (ties -> lowest index, matches ref)
        float tv[8]; int tj[8];
        #pragma unroll
        for (int j=0;j<8;j++){
            bool c = dd[2*j+1] > dd[2*j];
            tv[j] = c ? dd[2*j+1] : dd[2*j];
            tj[j] = c ? 2*j+1 : 2*j;
        }
        #pragma unroll
        for (int st=4; st>=1; st>>=1){
            #pragma unroll
            for (int j=0;j<st;j++){
                bool c = tv[2*j+1] > tv[2*j];
                tv[j] = c ? tv[2*j+1] : tv[2*j];
                tj[j] = c ? tj[2*j+1] : tj[2*j];
            }
        }
        float best = tv[0]; int bidx = base + tj[0];
        unsigned db   = __float_as_uint(best);        // >=0: uint order == float order
        unsigned wmax = __reduce_max_sync(FULLM, db);
        unsigned mk   = __ballot_sync(FULLM, db==wmax);
        int src = __ffs(mk)-1;                         // lowest lane = lowest index
        int par = it & 1;
        if (db==wmax && lane==src){                    // winner lane writes directly
            s_v[par][wid]=wmax; s_ix[par][wid]=(unsigned)bidx;
        }
        __syncthreads();
        unsigned vm   = s_v[par][lane & 7];
        unsigned bmax = __reduce_max_sync(FULLM, vm);
        unsigned mk2  = __ballot_sync(FULLM, vm==bmax);
        int src2 = __ffs(mk2)-1;                       // lowest warp = lowest index
        f = (int)s_ix[par][src2];
        cx=__ldg(X+f); cy=__ldg(X+NPT+f); cz=__ldg(X+2*NPT+f);   // broadcast L1 hit
    }
    __syncthreads();
    for (int i=t;i<3*NQ;i+=256){
        int c=i>>10, s=i&1023;
        out1[b*3072 + i] = X[c*NPT + g_fps[b*NQ+s]];
    }
}

// ---------------- ball query: packed f32x2 + early-empty ballot -----------
__global__ void __launch_bounds__(256) bq_kernel(const float* __restrict__ xyz,
                                                 const float* __restrict__ out1)
{
    __shared__ unsigned ebuf[8*128];
    int b = blockIdx.x >> 5, qb = blockIdx.x & 31;
    const float* Xx = xyz + b*3*NPT;
    const float* Xy = Xx + NPT;
    const float* Xz = Xx + 2*NPT;
    int wid = threadIdx.x>>5, lane = threadIdx.x&31;
    unsigned lt = (1u<<lane)-1u;
    unsigned* wbuf = ebuf + wid*128;
    int s0 = qb*32 + wid*4;
    float cx[4],cy[4],cz[4]; int cnt[4]={0,0,0,0}; unsigned gtag[4];
    unsigned long long ncx[4],ncy[4],ncz[4];
    #pragma unroll
    for (int q=0;q<4;q++){
        int s = s0+q;
        cx[q]=__ldg(out1 + b*3072 + s);
        cy[q]=__ldg(out1 + b*3072 + 1024 + s);
        cz[q]=__ldg(out1 + b*3072 + 2048 + s);
        ncx[q]=pk2(-cx[q],-cx[q]); ncy[q]=pk2(-cy[q],-cy[q]); ncz[q]=pk2(-cz[q],-cz[q]);
        gtag[q]=(unsigned)(b*NQ+s)<<12;
    }
    int wn = 0;
    for (int bp=0; bp<NPT; bp+=128){
        if (cnt[0]>=NSAMP && cnt[1]>=NSAMP && cnt[2]>=NSAMP && cnt[3]>=NSAMP) break;
        int p = bp + lane*4;
        float4 fx = __ldg((const float4*)(Xx+p));
        float4 fy = __ldg((const float4*)(Xy+p));
        float4 fz = __ldg((const float4*)(Xz+p));
        unsigned long long pxa=pk2(fx.x,fx.y), pxb=pk2(fx.z,fx.w);
        unsigned long long pya=pk2(fy.x,fy.y), pyb=pk2(fy.z,fy.w);
        unsigned long long pza=pk2(fz.x,fz.y), pzb=pk2(fz.z,fz.w);
        #pragma unroll
        for (int q=0;q<4;q++){
            if (cnt[q]>=NSAMP) continue;          // warp-uniform
            // packed distance eval: bitwise identical to scalar .rn sequence
            unsigned long long dxa=add2(pxa,ncx[q]), dya=add2(pya,ncy[q]), dza=add2(pza,ncz[q]);
            unsigned long long dxb=add2(pxb,ncx[q]), dyb=add2(pyb,ncy[q]), dzb=add2(pzb,ncz[q]);
            unsigned long long sa=add2(add2(mul2(dxa,dxa),mul2(dya,dya)),mul2(dza,dza));
            unsigned long long sb=add2(add2(mul2(dxb,dxb),mul2(dyb,dyb)),mul2(dzb,dzb));
            float d0,d1,d2,d3; upk2(sa,d0,d1); upk2(sb,d2,d3);
            bool inb[4] = { d0<=0.04f, d1<=0.04f, d2<=0.04f, d3<=0.04f };
            // early-empty: one ballot skips the 4 per-slot ballots (common case)
            if (!__ballot_sync(FULLM, inb[0]|inb[1]|inb[2]|inb[3])) continue;
            unsigned m[4];
            #pragma unroll
            for (int j=0;j<4;j++) m[j] = __ballot_sync(FULLM, inb[j]);
            int tot = __popc(m[0])+__popc(m[1])+__popc(m[2])+__popc(m[3]);
            if (cnt[q] + tot <= NSAMP){
                int off = wn;                      // order irrelevant downstream
                #pragma unroll
                for (int j=0;j<4;j++){
                    if (inb[j]) wbuf[off + __popc(m[j]&lt)] = gtag[q] | (unsigned)(p+j);
                    off += __popc(m[j]);
                }
                wn += tot; cnt[q] += tot;
            } else {
                // rare: crossing NSAMP — redo this 128-chunk in index order
                for (int sub=0; sub<4 && cnt[q]<NSAMP; ++sub){
                    int pp = bp + sub*32 + lane;
                    float dx=__ldg(Xx+pp)-cx[q], dy=__ldg(Xy+pp)-cy[q], dz=__ldg(Xz+pp)-cz[q];
                    float dsq = __fadd_rn(__fadd_rn(__fmul_rn(dx,dx),__fmul_rn(dy,dy)),__fmul_rn(dz,dz));
                    bool in = (dsq <= 0.04f);
                    unsigned mask = __ballot_sync(FULLM, in);
                    int pc = __popc(mask);
                    int take = min(pc, NSAMP-cnt[q]);
                    if (in){
                        int pos = __popc(mask & lt);
                        if (pos < take) wbuf[wn+pos] = gtag[q] | (unsigned)pp;
                    }
                    wn += take; cnt[q] += take;
                }
            }
        }
    }
    int gb = 0;
    if (lane==0) gb = atomicAdd(&g_ecnt, wn);
    gb = __shfl_sync(FULLM, gb, 0);
    for (int i=lane;i<wn;i+=32) g_ent[gb+i] = wbuf[i];
}

// ---------------- fused MLP: cp.async ping-pong prefetch + max scatter ----
// Buffers A/B (64 entries x 68 floats; 272B rows, 16B-aligned chunks).
// Tile t: input (entry-major) in I; L0 I->O (H, channel-major); L1 O->I
// (X2, channel-major); then cp.async gather of tile t+stride into O (dead)
// overlapping L2; wait_prior at next loop top.
__global__ void __launch_bounds__(256,4) mlp_kernel(const float* __restrict__ xyz,
                                                    float* __restrict__ out2)
{
    extern __shared__ float sm[];
    float* buf0 = sm;              // 4352
    float* buf1 = sm + 4352;       // 4352
    float* sB0  = sm + 8704;
    float* sB1  = sm + 8768;
    float* sB2  = sm + 8832;       // total 8960 floats = 35840 B
    int t = threadIdx.x;
    if (t<64){ sB0[t]=g_B0[t]; sB1[t]=g_B1[t]; }
    if (t<128) sB2[t]=g_B2[t];
    int E = g_ecnt;
    int tiles = (E+63)>>6;
    int tx = t&15, ty = t>>4;
    int le = t>>2, sub = t&3;
    int* outI = (int*)out2;

    auto gather = [&](int tb, float* D){
        int ge = tb*64 + le;
        unsigned raw = g_ent[ge < E ? ge : 0] & 0x3FFFFFFu;
        int p = raw & 4095; int g = raw >> 12; int bb = g >> 10;
        const float* src = g_ptsT + ((size_t)(bb*NPT)+p)*64 + sub*16;
        float* dst = D + le*68 + sub*16;
        #pragma unroll
        for (int k=0;k<4;k++)
            __pipeline_memcpy_async(dst + k*4, src + k*4, 16);
        __pipeline_commit();
        if (sub == 0){
            int ci = g_fps[g];
            const float* xc = xyz + (size_t)(bb*3)*NPT;
            #pragma unroll
            for (int c=0;c<3;c++)
                D[le*68 + 64 + c] = __ldg(xc + c*NPT + p) - __ldg(xc + c*NPT + ci);
        }
    };

    int tb = blockIdx.x;
    int pb = 0;
    if (tb < tiles) gather(tb, buf0);
    for (; tb < tiles; tb += gridDim.x, pb ^= 1){
        float* I = pb ? buf1 : buf0;
        float* O = pb ? buf0 : buf1;
        __pipeline_wait_prior(0);
        __syncthreads();                       // input buffer I ready CTA-wide
        // ---- layer 0: entry-major I (entries tx+16i) -> H in O -----------
        float acc[4][4];
        #pragma unroll
        for (int j=0;j<4;j++){ float bb=sB0[ty*4+j];
            #pragma unroll
            for (int i=0;i<4;i++) acc[i][j]=bb; }
        #pragma unroll 2
        for (int k4=0;k4<16;k4++){
            float4 xv[4];
            #pragma unroll
            for (int i=0;i<4;i++) xv[i] = *(const float4*)&I[(tx+16*i)*68 + k4*4];
            #pragma unroll
            for (int cc=0;cc<4;cc++){
                float4 wv = __ldg((const float4*)&g_W0[(k4*4+cc)*64 + ty*4]);
                float wr[4]={wv.x,wv.y,wv.z,wv.w};
                #pragma unroll
                for (int i=0;i<4;i++){
                    float xi = ((const float*)&xv[i])[cc];
                    #pragma unroll
                    for (int j=0;j<4;j++) acc[i][j] = fmaf(xi, wr[j], acc[i][j]);
                }
            }
        }
        #pragma unroll
        for (int cc=0;cc<3;cc++){              // xyz channels (W0 rows 64..66)
            float4 wv = __ldg((const float4*)&g_W0[(64+cc)*64 + ty*4]);
            float wr[4]={wv.x,wv.y,wv.z,wv.w};
            #pragma unroll
            for (int i=0;i<4;i++){
                float xi = I[(tx+16*i)*68 + 64 + cc];
                #pragma unroll
                for (int j=0;j<4;j++) acc[i][j] = fmaf(xi, wr[j], acc[i][j]);
            }
        }
        #pragma unroll
        for (int j=0;j<4;j++)
            #pragma unroll
            for (int i=0;i<4;i++)
                O[(ty*4+j)*64 + tx + 16*i] = fmaxf(acc[i][j],0.f);
        __syncthreads();
        // ---- layer 1: H(O) -> X2 into I (channel-major, entries 4tx..) ---
        #pragma unroll
        for (int j=0;j<4;j++){ float bb=sB1[ty*4+j];
            #pragma unroll
            for (int i=0;i<4;i++) acc[i][j]=bb; }
        #pragma unroll 4
        for (int k=0;k<64;k++){
            float4 xv = *(const float4*)&O[k*64+tx*4];
            float4 wv = __ldg((const float4*)&g_W1[k*64+ty*4]);
            float xr[4]={xv.x,xv.y,xv.z,xv.w};
            float wr[4]={wv.x,wv.y,wv.z,wv.w};
            #pragma unroll
            for (int i=0;i<4;i++)
                #pragma unroll
                for (int j=0;j<4;j++) acc[i][j] = fmaf(xr[i],wr[j],acc[i][j]);
        }
        #pragma unroll
        for (int j=0;j<4;j++){
            float4 hv = make_float4(fmaxf(acc[0][j],0.f),fmaxf(acc[1][j],0.f),
                                    fmaxf(acc[2][j],0.f),fmaxf(acc[3][j],0.f));
            *(float4*)&I[(ty*4+j)*64 + tx*4] = hv;
        }
        __syncthreads();                       // O (H) now dead
        {   // prefetch next tile into O, drains behind L2 + next wait
            int tn = tb + gridDim.x;
            if (tn < tiles) gather(tn, O);
        }
        // ---- layer 2: 64 -> 128, two 4-wide halves + merged atomicMax ----
        unsigned gid[4];
        #pragma unroll
        for (int i=0;i<4;i++){
            int ge = tb*64 + tx*4 + i;
            gid[i] = (ge < E) ? ((g_ent[ge] >> 12) & 0x3FFFu) : 0xFFFFFFFFu;
        }
        #pragma unroll
        for (int h=0; h<2; h++){
            #pragma unroll
            for (int j=0;j<4;j++){ float bb=sB2[ty*8+h*4+j];
                #pragma unroll
                for (int i=0;i<4;i++) acc[i][j]=bb; }
            #pragma unroll 4
            for (int k=0;k<64;k++){
                float4 xv = *(const float4*)&I[k*64+tx*4];
                float4 wv = __ldg((const float4*)&g_W2[k*128+ty*8+h*4]);
                float xr[4]={xv.x,xv.y,xv.z,xv.w};
                float wr[4]={wv.x,wv.y,wv.z,wv.w};
                #pragma unroll
                for (int i=0;i<4;i++)
                    #pragma unroll
                    for (int j=0;j<4;j++) acc[i][j]=fmaf(xr[i],wr[j],acc[i][j]);
            }
            #pragma unroll
            for (int i=0;i<4;i++){
                if (gid[i]==0xFFFFFFFFu) continue;
                if (i>0 && gid[i]==gid[i-1]) continue;   // merged into earlier head
                float mv[4];
                #pragma unroll
                for (int j=0;j<4;j++) mv[j]=acc[i][j];
                #pragma unroll
                for (int i2=1;i2<4;i2++){
                    if (i+i2<4 && gid[i+i2]==gid[i]){
                        #pragma unroll
                        for (int j=0;j<4;j++) mv[j]=fmaxf(mv[j],acc[i+i2][j]);
                    }
                }
                int bb = gid[i]>>10, s = gid[i]&1023;
                int* po = outI + (bb*128 + ty*8 + h*4)*NQ + s;
                #pragma unroll
                for (int j=0;j<4;j++)
                    atomicMax(po + j*NQ, __float_as_int(fmaxf(mv[j],0.f)));
            }
        }
    }
}

extern "C" void kernel_launch(void* const* d_in, const int* in_sizes, int n_in,
                              void* d_out, int out_size)
{
    const float* xyz = (const float*)d_in[0];
    const float* pts = (const float*)d_in[1];
    float* out1 = (float*)d_out;
    float* out2 = out1 + OUT1SZ;

    prep_kernel<<<2048,256>>>(out2, pts,
        (const float*)d_in[2],(const float*)d_in[3],(const float*)d_in[4],
        (const float*)d_in[5],(const float*)d_in[6],(const float*)d_in[7],
        (const float*)d_in[8],(const float*)d_in[9],(const float*)d_in[10],
        (const float*)d_in[11],(const float*)d_in[12],(const float*)d_in[13],
        (const float*)d_in[14],(const float*)d_in[15],(const float*)d_in[16],
        (const float*)d_in[17],(const float*)d_in[18],(const float*)d_in[19]);
    fps_kernel<<<16,256>>>(xyz, out1);
    bq_kernel<<<512,256>>>(xyz, out1);
    mlp_kernel<<<592,256,35840>>>(xyz, out2);
}